// round 12
// baseline (speedup 1.0000x reference)
#include <cuda_runtime.h>
#include <cuda_bf16.h>
#include <math.h>
#include <stdint.h>

#define B_ROWS 16384
#define N0     2048
#define NCLS   12
#define NCLU   24
#define NDIM   4
#define NCOL   348
#define NPAD   384

// GEMM tiling
#define BM 128
#define BN 96
#define BK 32
#define THREADS 256
#define KCHUNKS (N0 / BK)     // 64

// smem stage layout (bytes); rows padded to 40 bf16 (80B) => conflict-free ldmatrix
#define ST_AH 0
#define ST_AL 10240           // 128*80
#define ST_BH 20480
#define ST_BL 28160           // + 96*80
#define STAGE 35840
#define SMEM_TOTAL (2 * STAGE)  // 71680

#define FLAG_THRESH 1.2e-4f

// ----------------------------- device scratch ------------------------------
__device__ float g_Wc[NCOL * N0];                  // fp32 packed weights [j][k] (fixup)
__device__ float g_bias[NPAD];
__device__ float g_Y[(size_t)B_ROWS * NPAD];       // GEMM output
__device__ __align__(16) __nv_bfloat16 g_Bh[NPAD * N0];  // W^T hi, [n][k]
__device__ __align__(16) __nv_bfloat16 g_Bl[NPAD * N0];  // W^T lo, [n][k]
__device__ int g_flagcnt;
__device__ int g_flagrows[B_ROWS];                 // row | (candidate mask << 14)

// output layout (tuple concat) — validated in round 1
#define Y0_OFF   0
#define Y1_OFF   ((size_t)B_ROWS * 12)
#define Y2_OFF   ((size_t)B_ROWS * 36)
#define PLC_OFF  ((size_t)B_ROWS * 40)

// ----------------------------- PTX helpers ---------------------------------
__device__ __forceinline__ uint32_t smem_u32(const void* p) {
    uint32_t a;
    asm("{ .reg .u64 t; cvta.to.shared.u64 t, %1; cvt.u32.u64 %0, t; }" : "=r"(a) : "l"(p));
    return a;
}
#define CP_ASYNC16(dst, src) \
    asm volatile("cp.async.cg.shared.global [%0], [%1], 16;" :: "r"(dst), "l"(src))
#define CP_COMMIT() asm volatile("cp.async.commit_group;" ::: "memory")
#define CP_WAIT0()  asm volatile("cp.async.wait_group 0;" ::: "memory")

#define LDMATRIX_X4(r0, r1, r2, r3, addr) \
    asm volatile("ldmatrix.sync.aligned.m8n8.x4.shared.b16 {%0,%1,%2,%3}, [%4];" \
                 : "=r"(r0), "=r"(r1), "=r"(r2), "=r"(r3) : "r"(addr))

#define MMA_BF16(d, a, b0, b1) \
    asm volatile("mma.sync.aligned.m16n8k16.row.col.f32.bf16.bf16.f32 " \
                 "{%0,%1,%2,%3}, {%4,%5,%6,%7}, {%8,%9}, {%0,%1,%2,%3};" \
                 : "+f"((d)[0]), "+f"((d)[1]), "+f"((d)[2]), "+f"((d)[3]) \
                 : "r"((a)[0]), "r"((a)[1]), "r"((a)[2]), "r"((a)[3]), "r"(b0), "r"(b1))

// ----------------------------- packing -------------------------------------
__device__ __forceinline__ float colval(int j, int k, const float* Wfc,
                                        const float* Wbin, const float* Wres) {
    if (j < 12) return Wfc[k * NCLS + j];
    if (j < 300) { int t = j - 12, c = t / NCLU, kk = t - c * NCLU;
                   return Wbin[((size_t)c * N0 + k) * NCLU + kk]; }
    if (j < NCOL) { int t = j - 300, c = t / NDIM, n = t - c * NDIM;
                    return Wres[((size_t)c * N0 + k) * NDIM + n]; }
    return 0.f;
}

#define PACK_R2 (NPAD * (N0 / 8))           // bf16 hi/lo tasks
#define PACK_R3 (NCOL * (N0 / 4))           // g_Wc float4 tasks
#define PACK_TASKS (PACK_R2 + PACK_R3)

__global__ void pack_kernel(const float* __restrict__ Wfc,  const float* __restrict__ bfc,
                            const float* __restrict__ Wbin, const float* __restrict__ bbin,
                            const float* __restrict__ Wres, const float* __restrict__ bres) {
    int idx = blockIdx.x * blockDim.x + threadIdx.x;
    if (idx == 0) g_flagcnt = 0;
    if (idx < NPAD) {
        float bv = 0.f;
        if (idx < 12) bv = bfc[idx];
        else if (idx < 300) { int t = idx - 12, c = t / NCLU, kk = t - c * NCLU; bv = bbin[c * NCLU + kk]; }
        else if (idx < NCOL) { int t = idx - 300, c = t / NDIM, n = t - c * NDIM; bv = bres[c * NDIM + n]; }
        g_bias[idx] = bv;
    }
    // region 2: bf16 hi/lo transposed weights [n][k], 8 k per thread
    if (idx < PACK_R2) {
        int n = idx / (N0 / 8);
        int k0 = (idx % (N0 / 8)) * 8;
        float v[8];
#pragma unroll
        for (int e = 0; e < 8; e++) v[e] = colval(n, k0 + e, Wfc, Wbin, Wres);
        uint32_t hp[4], lp[4];
#pragma unroll
        for (int i = 0; i < 4; i++) {
            __nv_bfloat162 h2 = __floats2bfloat162_rn(v[2*i], v[2*i+1]);
            float r0 = v[2*i]   - __bfloat162float(h2.x);
            float r1 = v[2*i+1] - __bfloat162float(h2.y);
            __nv_bfloat162 l2 = __floats2bfloat162_rn(r0, r1);
            hp[i] = *reinterpret_cast<uint32_t*>(&h2);
            lp[i] = *reinterpret_cast<uint32_t*>(&l2);
        }
        *reinterpret_cast<uint4*>(&g_Bh[n * N0 + k0]) = make_uint4(hp[0], hp[1], hp[2], hp[3]);
        *reinterpret_cast<uint4*>(&g_Bl[n * N0 + k0]) = make_uint4(lp[0], lp[1], lp[2], lp[3]);
    }
    // region 3: column-major fp32 weights g_Wc[j][k], float4 per thread
    int t3 = idx - PACK_R2;
    if (t3 >= 0 && t3 < PACK_R3) {
        int col = t3 / (N0 / 4);
        int k0  = (t3 % (N0 / 4)) * 4;
        float4 v;
        v.x = colval(col, k0 + 0, Wfc, Wbin, Wres);
        v.y = colval(col, k0 + 1, Wfc, Wbin, Wres);
        v.z = colval(col, k0 + 2, Wfc, Wbin, Wres);
        v.w = colval(col, k0 + 3, Wfc, Wbin, Wres);
        *reinterpret_cast<float4*>(&g_Wc[col * N0 + k0]) = v;
    }
}

// ----------------------------- mma.sync GEMM -------------------------------
// Y[16384][384] = x @ W (+bias), 3-term bf16 split, fp32 accum.
// Rescheduled: storeA/loadB issued BEFORE compute so the post-compute tail is
// just wait+sync; A fp32 regs double-buffered (aregA/aregB).
__global__ __launch_bounds__(THREADS, 2) void gemm_kernel(const float* __restrict__ x) {
    extern __shared__ char smem[];
    const uint32_t sb = smem_u32(smem);
    const int tid  = threadIdx.x;
    const int lane = tid & 31;
    const int wid  = tid >> 5;
    const int wm   = wid >> 1;          // 0..3
    const int wn   = wid & 1;           // 0..1
    const int bm   = blockIdx.y * BM;
    const int bn   = blockIdx.x * BN;

    float acc[2][6][4];
#pragma unroll
    for (int i = 0; i < 2; i++)
#pragma unroll
        for (int j = 0; j < 6; j++)
#pragma unroll
            for (int q = 0; q < 4; q++) acc[i][j][q] = 0.f;

    auto loadB = [&](int c, int s) {
#pragma unroll
        for (int it = 0; it < 3; ++it) {
            int g = tid + it * 256;                 // 0..767
            int half = (g >= 384);
            int idx2 = g - half * 384;
            int row = idx2 >> 2, seg = idx2 & 3;
            const __nv_bfloat16* src = (half ? g_Bl : g_Bh)
                                     + (size_t)(bn + row) * N0 + c * BK + seg * 8;
            uint32_t dst = sb + s * STAGE + (half ? ST_BL : ST_BH) + row * 80 + seg * 16;
            CP_ASYNC16(dst, src);
        }
        CP_COMMIT();
    };
    float4 aregA[4], aregB[4];
    auto loadA = [&](float4* ar, int c) {
#pragma unroll
        for (int it = 0; it < 4; ++it) {
            int idx2 = tid + it * 256;              // 0..1023
            int row = idx2 >> 3, seg = idx2 & 7;
            ar[it] = *reinterpret_cast<const float4*>(
                x + (size_t)(bm + row) * N0 + c * BK + seg * 4);
        }
    };
    auto storeA = [&](const float4* ar, int s) {
#pragma unroll
        for (int it = 0; it < 4; ++it) {
            int idx2 = tid + it * 256;
            int row = idx2 >> 3, seg = idx2 & 7;
            float v[4] = {ar[it].x, ar[it].y, ar[it].z, ar[it].w};
            uint32_t hp[2], lp[2];
#pragma unroll
            for (int i = 0; i < 2; i++) {
                __nv_bfloat162 h2 = __floats2bfloat162_rn(v[2*i], v[2*i+1]);
                float r0 = v[2*i]   - __bfloat162float(h2.x);
                float r1 = v[2*i+1] - __bfloat162float(h2.y);
                __nv_bfloat162 l2 = __floats2bfloat162_rn(r0, r1);
                hp[i] = *reinterpret_cast<uint32_t*>(&h2);
                lp[i] = *reinterpret_cast<uint32_t*>(&l2);
            }
            char* base = smem + s * STAGE;
            *reinterpret_cast<uint2*>(base + ST_AH + row * 80 + seg * 8) = make_uint2(hp[0], hp[1]);
            *reinterpret_cast<uint2*>(base + ST_AL + row * 80 + seg * 8) = make_uint2(lp[0], lp[1]);
        }
    };

    auto compute = [&](int s) {
        const uint32_t st = sb + s * STAGE;
        const int arow = wm * 32 + (lane & 15);
        const int acol8 = (lane >> 4) * 8;
        const int brow = wn * 48 + ((lane >> 4) & 1) * 8 + (lane & 7);
        const int bcol8 = ((lane >> 3) & 1) * 8;
#pragma unroll
        for (int kk = 0; kk < BK; kk += 16) {
            uint32_t ah[2][4], al[2][4], b[3][4];
#pragma unroll
            for (int mf = 0; mf < 2; mf++) {
                uint32_t ad = st + ST_AH + (arow + mf * 16) * 80 + (kk + acol8) * 2;
                LDMATRIX_X4(ah[mf][0], ah[mf][1], ah[mf][2], ah[mf][3], ad);
                uint32_t adl = st + ST_AL + (arow + mf * 16) * 80 + (kk + acol8) * 2;
                LDMATRIX_X4(al[mf][0], al[mf][1], al[mf][2], al[mf][3], adl);
            }
#pragma unroll
            for (int bq = 0; bq < 3; bq++) {
                uint32_t bd = st + ST_BH + (brow + bq * 16) * 80 + (kk + bcol8) * 2;
                LDMATRIX_X4(b[bq][0], b[bq][1], b[bq][2], b[bq][3], bd);
            }
#pragma unroll
            for (int mf = 0; mf < 2; mf++)
#pragma unroll
                for (int nf = 0; nf < 6; nf++) {
                    int bq = nf >> 1, o = (nf & 1) * 2;
                    MMA_BF16(acc[mf][nf], ah[mf], b[bq][o], b[bq][o + 1]);
                    MMA_BF16(acc[mf][nf], al[mf], b[bq][o], b[bq][o + 1]);
                }
#pragma unroll
            for (int bq = 0; bq < 3; bq++) {
                uint32_t bd = st + ST_BL + (brow + bq * 16) * 80 + (kk + bcol8) * 2;
                LDMATRIX_X4(b[bq][0], b[bq][1], b[bq][2], b[bq][3], bd);
            }
#pragma unroll
            for (int mf = 0; mf < 2; mf++)
#pragma unroll
                for (int nf = 0; nf < 6; nf++) {
                    int bq = nf >> 1, o = (nf & 1) * 2;
                    MMA_BF16(acc[mf][nf], ah[mf], b[bq][o], b[bq][o + 1]);
                }
        }
    };

    // prologue: stage 0 filled with chunk 0; a1 preloaded into aregB
    loadA(aregA, 0);
    storeA(aregA, 0);
    loadB(0, 0);
    loadA(aregB, 1);
    CP_WAIT0();
    __syncthreads();

    for (int c = 0; c < KCHUNKS; ++c) {
        int s = c & 1;
        if (c + 1 < KCHUNKS) {
            loadB(c + 1, s ^ 1);
            // a_{c+1} lives in aregB when c even, aregA when c odd
            storeA((c & 1) ? aregA : aregB, s ^ 1);
            if (c + 2 < KCHUNKS)
                loadA((c & 1) ? aregB : aregA, c + 2);   // refill consumed buffer
        }
        compute(s);
        if (c + 1 < KCHUNKS) {
            CP_WAIT0();
            __syncthreads();
        }
    }

#pragma unroll
    for (int mf = 0; mf < 2; mf++) {
        int r0 = bm + wm * 32 + mf * 16 + (lane >> 2);
#pragma unroll
        for (int nf = 0; nf < 6; nf++) {
            int col = bn + wn * 48 + nf * 8 + (lane & 3) * 2;
            float2 v0 = make_float2(acc[mf][nf][0] + g_bias[col],
                                    acc[mf][nf][1] + g_bias[col + 1]);
            float2 v1 = make_float2(acc[mf][nf][2] + g_bias[col],
                                    acc[mf][nf][3] + g_bias[col + 1]);
            *reinterpret_cast<float2*>(g_Y + (size_t)r0 * NPAD + col) = v0;
            *reinterpret_cast<float2*>(g_Y + (size_t)(r0 + 8) * NPAD + col) = v1;
        }
    }
}

// ----------------------------- epilogue ------------------------------------
__global__ __launch_bounds__(256) void epilogue_kernel(float* __restrict__ out) {
    const int warp = threadIdx.x >> 5;
    const int lane = threadIdx.x & 31;
    const int row  = blockIdx.x * 8 + warp;

    __shared__ float sY[8][352];
    __shared__ float sP[8][288];

    {
        const float4* yr4 = reinterpret_cast<const float4*>(g_Y + (size_t)row * NPAD);
        float4* sy4 = reinterpret_cast<float4*>(sY[warp]);
#pragma unroll
        for (int j = lane; j < 87; j += 32) sy4[j] = yr4[j];
    }
    __syncwarp();
    const float* s = sY[warp];

    float y0v = (lane < NCLS) ? s[lane] : -INFINITY;
    float m = y0v;
#pragma unroll
    for (int o = 16; o; o >>= 1) m = fmaxf(m, __shfl_xor_sync(0xFFFFFFFFu, m, o));
    float e = (lane < NCLS) ? __expf(y0v - m) : 0.f;
    float ssum = e;
#pragma unroll
    for (int o = 16; o; o >>= 1) ssum += __shfl_xor_sync(0xFFFFFFFFu, ssum, o);
    float Pc = e / ssum;

    float best = -1.f;
    int bestk = 0;
    if (lane < NCLS) {
        const float* yc = s + 12 + lane * NCLU;
        float mc = -INFINITY;
#pragma unroll
        for (int k = 0; k < NCLU; k++) mc = fmaxf(mc, yc[k]);
        float sc = 0.f;
#pragma unroll
        for (int k = 0; k < NCLU; k++) sc += __expf(yc[k] - mc);
        float inv = Pc / sc;
#pragma unroll
        for (int k = 0; k < NCLU; k++) {
            float p = __expf(yc[k] - mc) * inv;
            sP[warp][k * NCLS + lane] = p;
            if (p > best) { best = p; bestk = k; }
        }
    }
    __syncwarp();

    // coalesced Plc writes: 72 float4 per row
    {
        const float4* sp4 = reinterpret_cast<const float4*>(sP[warp]);
        float4* po4 = reinterpret_cast<float4*>(out + PLC_OFF + (size_t)row * (NCLU * NCLS));
#pragma unroll
        for (int j = lane; j < 72; j += 32) po4[j] = sp4[j];
    }

    // argmax with first-flat-index tie-break
    float bv = best;
    int bi = bestk * NCLS + lane;
#pragma unroll
    for (int o = 16; o; o >>= 1) {
        float ov = __shfl_xor_sync(0xFFFFFFFFu, bv, o);
        int   oi = __shfl_xor_sync(0xFFFFFFFFu, bi, o);
        if (ov > bv || (ov == bv && oi < bi)) { bv = ov; bi = oi; }
    }
    const int ic = bi % NCLS;

    // candidate-class mask: classes whose per-class best Plc is within thresh of max
    unsigned cmask = __ballot_sync(0xFFFFFFFFu,
                                   (lane < NCLS) && (best >= bv - FLAG_THRESH * bv)) & 0xFFFu;
    if (lane == 0 && (cmask & (cmask - 1))) {   // >1 candidate class
        int p = atomicAdd(&g_flagcnt, 1);
        g_flagrows[p] = row | ((int)cmask << 14);
    }

    if (lane < NCLS) out[Y0_OFF + (size_t)row * NCLS + lane] = s[lane];
    if (lane < NCLU) out[Y1_OFF + (size_t)row * NCLU + lane] = s[12 + ic * NCLU + lane];
    if (lane < NDIM) out[Y2_OFF + (size_t)row * NDIM + lane] = s[300 + ic * NDIM + lane];
}

// ----------------------------- fp32 exact fixup (candidate classes only) ---
__global__ __launch_bounds__(1024) void fixup_kernel(const float* __restrict__ x,
                                                     float* __restrict__ out) {
    __shared__ float sx[N0];
    __shared__ float sy[NCOL];
    __shared__ int   wl[12 + NCLS * NCLU];
    __shared__ int   s_nwork;
    const int tid  = threadIdx.x;
    const int lane = tid & 31;
    const int wid  = tid >> 5;
    const int cnt  = g_flagcnt;

    for (int f = blockIdx.x; f < cnt; f += gridDim.x) {
        const int packed = g_flagrows[f];
        const int row   = packed & 0x3FFF;
        const int cmask = (packed >> 14) & 0xFFF;

        if (tid < 512) {
            *reinterpret_cast<float4*>(&sx[tid * 4]) =
                *reinterpret_cast<const float4*>(x + (size_t)row * N0 + tid * 4);
        }
        if (tid < 12) wl[tid] = tid;
        if (tid < 12 && (cmask >> tid) & 1) {
            int pos = __popc(cmask & ((1 << tid) - 1));
            for (int k = 0; k < NCLU; k++)
                wl[12 + pos * NCLU + k] = 12 + tid * NCLU + k;
        }
        if (tid == 0) s_nwork = 12 + NCLU * __popc(cmask);
        __syncthreads();
        const int nwork = s_nwork;

        for (int w = wid; w < nwork; w += 32) {
            int col = wl[w];
            const float4* wp = reinterpret_cast<const float4*>(&g_Wc[col * N0]);
            const float4* xp = reinterpret_cast<const float4*>(sx);
            float acc = 0.f;
#pragma unroll 8
            for (int i = lane; i < N0 / 4; i += 32) {
                float4 a = xp[i], b = wp[i];
                acc += a.x * b.x + a.y * b.y + a.z * b.z + a.w * b.w;
            }
#pragma unroll
            for (int o = 16; o; o >>= 1) acc += __shfl_xor_sync(0xFFFFFFFFu, acc, o);
            if (lane == 0) sy[col] = acc + g_bias[col];
        }
        __syncthreads();

        if (tid == 0) {
            float mm = -INFINITY;
            for (int c = 0; c < NCLS; c++) mm = fmaxf(mm, sy[c]);
            float ss = 0.f;
            for (int c = 0; c < NCLS; c++) ss += expf(sy[c] - mm);

            float bp = -1.f; int bi = 0x7FFFFFFF;
            for (int c = 0; c < NCLS; c++) {
                if (!((cmask >> c) & 1)) continue;
                float Pc = expf(sy[c] - mm) / ss;
                const float* yc = sy + 12 + c * NCLU;
                float mc = -INFINITY;
                for (int k = 0; k < NCLU; k++) mc = fmaxf(mc, yc[k]);
                float sc = 0.f;
                for (int k = 0; k < NCLU; k++) sc += expf(yc[k] - mc);
                float inv = Pc / sc;
                for (int k = 0; k < NCLU; k++) {
                    float p = expf(yc[k] - mc) * inv;
                    int flat = k * NCLS + c;
                    if (p > bp || (p == bp && flat < bi)) { bp = p; bi = flat; }
                }
            }
            int ic = bi % NCLS;
            const float* yr = g_Y + (size_t)row * NPAD;
            for (int k = 0; k < NCLU; k++)
                out[Y1_OFF + (size_t)row * NCLU + k] = yr[12 + ic * NCLU + k];
            for (int n = 0; n < NDIM; n++)
                out[Y2_OFF + (size_t)row * NDIM + n] = yr[300 + ic * NDIM + n];
        }
        __syncthreads();
    }
}

// ============================================================================
extern "C" void kernel_launch(void* const* d_in, const int* in_sizes, int n_in,
                              void* d_out, int out_size) {
    const float* x    = (const float*)d_in[0];
    const float* Wfc  = (const float*)d_in[1];
    const float* bfc  = (const float*)d_in[2];
    const float* Wbin = (const float*)d_in[3];
    const float* bbin = (const float*)d_in[4];
    const float* Wres = (const float*)d_in[5];
    const float* bres = (const float*)d_in[6];
    float* out = (float*)d_out;

    static bool attr_set = false;
    if (!attr_set) {
        cudaFuncSetAttribute(gemm_kernel, cudaFuncAttributeMaxDynamicSharedMemorySize, SMEM_TOTAL);
        attr_set = true;
    }

    pack_kernel<<<(PACK_TASKS + 255) / 256, 256>>>(Wfc, bfc, Wbin, bbin, Wres, bres);

    gemm_kernel<<<dim3(NPAD / BN, B_ROWS / BM), THREADS, SMEM_TOTAL>>>(x);

    epilogue_kernel<<<B_ROWS / 8, 256>>>(out);

    fixup_kernel<<<1024, 1024>>>(x, out);
}

// round 16
// speedup vs baseline: 1.1409x; 1.1409x over previous
#include <cuda_runtime.h>
#include <cuda_bf16.h>
#include <math.h>
#include <stdint.h>

#define B_ROWS 16384
#define N0     2048
#define NCLS   12
#define NCLU   24
#define NDIM   4
#define NCOL   348
#define NPAD   384

// GEMM tiling
#define BM 128
#define BN 96
#define BK 32
#define THREADS 256
#define KCHUNKS (N0 / BK)     // 64

// smem stage layout (bytes); rows padded to 40 bf16 (80B) => conflict-free ldmatrix
#define ST_AH 0
#define ST_AL 10240           // 128*80
#define ST_BH 20480
#define ST_BL 28160           // + 96*80
#define STAGE 35840
#define SMEM_TOTAL (2 * STAGE)  // 71680

#define FLAG_THRESH 1.2e-4f

// ----------------------------- device scratch ------------------------------
__device__ float g_Wc[NCOL * N0];                  // fp32 packed weights [j][k] (fixup)
__device__ float g_bias[NPAD];
__device__ float g_Y[(size_t)B_ROWS * NPAD];       // GEMM output
__device__ __align__(16) __nv_bfloat16 g_Bh[NPAD * N0];  // W^T hi, [n][k]
__device__ __align__(16) __nv_bfloat16 g_Bl[NPAD * N0];  // W^T lo, [n][k]
__device__ int g_flagcnt;
__device__ int g_flagrows[B_ROWS];                 // row | (candidate mask << 14)

// output layout (tuple concat) — validated in round 1
#define Y0_OFF   0
#define Y1_OFF   ((size_t)B_ROWS * 12)
#define Y2_OFF   ((size_t)B_ROWS * 36)
#define PLC_OFF  ((size_t)B_ROWS * 40)

// ----------------------------- PTX helpers ---------------------------------
__device__ __forceinline__ uint32_t smem_u32(const void* p) {
    uint32_t a;
    asm("{ .reg .u64 t; cvta.to.shared.u64 t, %1; cvt.u32.u64 %0, t; }" : "=r"(a) : "l"(p));
    return a;
}
#define CP_ASYNC16(dst, src) \
    asm volatile("cp.async.cg.shared.global [%0], [%1], 16;" :: "r"(dst), "l"(src))
#define CP_COMMIT() asm volatile("cp.async.commit_group;" ::: "memory")
#define CP_WAIT0()  asm volatile("cp.async.wait_group 0;" ::: "memory")

#define LDMATRIX_X4(r0, r1, r2, r3, addr) \
    asm volatile("ldmatrix.sync.aligned.m8n8.x4.shared.b16 {%0,%1,%2,%3}, [%4];" \
                 : "=r"(r0), "=r"(r1), "=r"(r2), "=r"(r3) : "r"(addr))

#define MMA_BF16(d, a, b0, b1) \
    asm volatile("mma.sync.aligned.m16n8k16.row.col.f32.bf16.bf16.f32 " \
                 "{%0,%1,%2,%3}, {%4,%5,%6,%7}, {%8,%9}, {%0,%1,%2,%3};" \
                 : "+f"((d)[0]), "+f"((d)[1]), "+f"((d)[2]), "+f"((d)[3]) \
                 : "r"((a)[0]), "r"((a)[1]), "r"((a)[2]), "r"((a)[3]), "r"(b0), "r"(b1))

// ----------------------------- packing -------------------------------------
__device__ __forceinline__ float colval(int j, int k, const float* Wfc,
                                        const float* Wbin, const float* Wres) {
    if (j < 12) return Wfc[k * NCLS + j];
    if (j < 300) { int t = j - 12, c = t / NCLU, kk = t - c * NCLU;
                   return Wbin[((size_t)c * N0 + k) * NCLU + kk]; }
    if (j < NCOL) { int t = j - 300, c = t / NDIM, n = t - c * NDIM;
                    return Wres[((size_t)c * N0 + k) * NDIM + n]; }
    return 0.f;
}

#define PACK_R2 (NPAD * (N0 / 8))           // bf16 hi/lo tasks
#define PACK_R3 (NCOL * (N0 / 4))           // g_Wc float4 tasks
#define PACK_TASKS (PACK_R2 + PACK_R3)

__global__ void pack_kernel(const float* __restrict__ Wfc,  const float* __restrict__ bfc,
                            const float* __restrict__ Wbin, const float* __restrict__ bbin,
                            const float* __restrict__ Wres, const float* __restrict__ bres) {
    int idx = blockIdx.x * blockDim.x + threadIdx.x;
    if (idx == 0) g_flagcnt = 0;
    if (idx < NPAD) {
        float bv = 0.f;
        if (idx < 12) bv = bfc[idx];
        else if (idx < 300) { int t = idx - 12, c = t / NCLU, kk = t - c * NCLU; bv = bbin[c * NCLU + kk]; }
        else if (idx < NCOL) { int t = idx - 300, c = t / NDIM, n = t - c * NDIM; bv = bres[c * NDIM + n]; }
        g_bias[idx] = bv;
    }
    // region 2: bf16 hi/lo transposed weights [n][k], 8 k per thread
    if (idx < PACK_R2) {
        int n = idx / (N0 / 8);
        int k0 = (idx % (N0 / 8)) * 8;
        float v[8];
#pragma unroll
        for (int e = 0; e < 8; e++) v[e] = colval(n, k0 + e, Wfc, Wbin, Wres);
        uint32_t hp[4], lp[4];
#pragma unroll
        for (int i = 0; i < 4; i++) {
            __nv_bfloat162 h2 = __floats2bfloat162_rn(v[2*i], v[2*i+1]);
            float r0 = v[2*i]   - __bfloat162float(h2.x);
            float r1 = v[2*i+1] - __bfloat162float(h2.y);
            __nv_bfloat162 l2 = __floats2bfloat162_rn(r0, r1);
            hp[i] = *reinterpret_cast<uint32_t*>(&h2);
            lp[i] = *reinterpret_cast<uint32_t*>(&l2);
        }
        *reinterpret_cast<uint4*>(&g_Bh[n * N0 + k0]) = make_uint4(hp[0], hp[1], hp[2], hp[3]);
        *reinterpret_cast<uint4*>(&g_Bl[n * N0 + k0]) = make_uint4(lp[0], lp[1], lp[2], lp[3]);
    }
    // region 3: column-major fp32 weights g_Wc[j][k], float4 per thread
    int t3 = idx - PACK_R2;
    if (t3 >= 0 && t3 < PACK_R3) {
        int col = t3 / (N0 / 4);
        int k0  = (t3 % (N0 / 4)) * 4;
        float4 v;
        v.x = colval(col, k0 + 0, Wfc, Wbin, Wres);
        v.y = colval(col, k0 + 1, Wfc, Wbin, Wres);
        v.z = colval(col, k0 + 2, Wfc, Wbin, Wres);
        v.w = colval(col, k0 + 3, Wfc, Wbin, Wres);
        *reinterpret_cast<float4*>(&g_Wc[col * N0 + k0]) = v;
    }
}

// ----------------------------- mma.sync GEMM -------------------------------
// Y[16384][384] = x @ W (+bias), 3-term bf16 split, fp32 accum.
// Round-11 proven schedule: loadB/loadA -> compute -> storeA -> wait -> sync.
__global__ __launch_bounds__(THREADS) void gemm_kernel(const float* __restrict__ x) {
    extern __shared__ char smem[];
    const uint32_t sb = smem_u32(smem);
    const int tid  = threadIdx.x;
    const int lane = tid & 31;
    const int wid  = tid >> 5;
    const int wm   = wid >> 1;          // 0..3
    const int wn   = wid & 1;           // 0..1
    const int bm   = blockIdx.y * BM;
    const int bn   = blockIdx.x * BN;

    float acc[2][6][4];
#pragma unroll
    for (int i = 0; i < 2; i++)
#pragma unroll
        for (int j = 0; j < 6; j++)
#pragma unroll
            for (int q = 0; q < 4; q++) acc[i][j][q] = 0.f;

    auto loadB = [&](int c, int s) {
#pragma unroll
        for (int it = 0; it < 3; ++it) {
            int g = tid + it * 256;                 // 0..767
            int half = (g >= 384);
            int idx2 = g - half * 384;
            int row = idx2 >> 2, seg = idx2 & 3;
            const __nv_bfloat16* src = (half ? g_Bl : g_Bh)
                                     + (size_t)(bn + row) * N0 + c * BK + seg * 8;
            uint32_t dst = sb + s * STAGE + (half ? ST_BL : ST_BH) + row * 80 + seg * 16;
            CP_ASYNC16(dst, src);
        }
        CP_COMMIT();
    };
    float4 areg[4];
    auto loadA = [&](int c) {
#pragma unroll
        for (int it = 0; it < 4; ++it) {
            int idx2 = tid + it * 256;              // 0..1023
            int row = idx2 >> 3, seg = idx2 & 7;
            areg[it] = *reinterpret_cast<const float4*>(
                x + (size_t)(bm + row) * N0 + c * BK + seg * 4);
        }
    };
    auto storeA = [&](int s) {
#pragma unroll
        for (int it = 0; it < 4; ++it) {
            int idx2 = tid + it * 256;
            int row = idx2 >> 3, seg = idx2 & 7;
            float v[4] = {areg[it].x, areg[it].y, areg[it].z, areg[it].w};
            uint32_t hp[2], lp[2];
#pragma unroll
            for (int i = 0; i < 2; i++) {
                __nv_bfloat162 h2 = __floats2bfloat162_rn(v[2*i], v[2*i+1]);
                float r0 = v[2*i]   - __bfloat162float(h2.x);
                float r1 = v[2*i+1] - __bfloat162float(h2.y);
                __nv_bfloat162 l2 = __floats2bfloat162_rn(r0, r1);
                hp[i] = *reinterpret_cast<uint32_t*>(&h2);
                lp[i] = *reinterpret_cast<uint32_t*>(&l2);
            }
            char* base = smem + s * STAGE;
            *reinterpret_cast<uint2*>(base + ST_AH + row * 80 + seg * 8) = make_uint2(hp[0], hp[1]);
            *reinterpret_cast<uint2*>(base + ST_AL + row * 80 + seg * 8) = make_uint2(lp[0], lp[1]);
        }
    };

    auto compute = [&](int s) {
        const uint32_t st = sb + s * STAGE;
        const int arow = wm * 32 + (lane & 15);
        const int acol8 = (lane >> 4) * 8;
        const int brow = wn * 48 + ((lane >> 4) & 1) * 8 + (lane & 7);
        const int bcol8 = ((lane >> 3) & 1) * 8;
#pragma unroll
        for (int kk = 0; kk < BK; kk += 16) {
            uint32_t ah[2][4], al[2][4], b[3][4];
#pragma unroll
            for (int mf = 0; mf < 2; mf++) {
                uint32_t ad = st + ST_AH + (arow + mf * 16) * 80 + (kk + acol8) * 2;
                LDMATRIX_X4(ah[mf][0], ah[mf][1], ah[mf][2], ah[mf][3], ad);
                uint32_t adl = st + ST_AL + (arow + mf * 16) * 80 + (kk + acol8) * 2;
                LDMATRIX_X4(al[mf][0], al[mf][1], al[mf][2], al[mf][3], adl);
            }
#pragma unroll
            for (int bq = 0; bq < 3; bq++) {
                uint32_t bd = st + ST_BH + (brow + bq * 16) * 80 + (kk + bcol8) * 2;
                LDMATRIX_X4(b[bq][0], b[bq][1], b[bq][2], b[bq][3], bd);
            }
#pragma unroll
            for (int mf = 0; mf < 2; mf++)
#pragma unroll
                for (int nf = 0; nf < 6; nf++) {
                    int bq = nf >> 1, o = (nf & 1) * 2;
                    MMA_BF16(acc[mf][nf], ah[mf], b[bq][o], b[bq][o + 1]);
                    MMA_BF16(acc[mf][nf], al[mf], b[bq][o], b[bq][o + 1]);
                }
#pragma unroll
            for (int bq = 0; bq < 3; bq++) {
                uint32_t bd = st + ST_BL + (brow + bq * 16) * 80 + (kk + bcol8) * 2;
                LDMATRIX_X4(b[bq][0], b[bq][1], b[bq][2], b[bq][3], bd);
            }
#pragma unroll
            for (int mf = 0; mf < 2; mf++)
#pragma unroll
                for (int nf = 0; nf < 6; nf++) {
                    int bq = nf >> 1, o = (nf & 1) * 2;
                    MMA_BF16(acc[mf][nf], ah[mf], b[bq][o], b[bq][o + 1]);
                }
        }
    };

    loadB(0, 0);
    loadA(0);
    storeA(0);
    CP_WAIT0();
    __syncthreads();
    for (int c = 0; c < KCHUNKS; ++c) {
        int s = c & 1;
        if (c < KCHUNKS - 1) { loadB(c + 1, s ^ 1); loadA(c + 1); }
        compute(s);
        if (c < KCHUNKS - 1) {
            storeA(s ^ 1);
            CP_WAIT0();
            __syncthreads();
        }
    }

#pragma unroll
    for (int mf = 0; mf < 2; mf++) {
        int r0 = bm + wm * 32 + mf * 16 + (lane >> 2);
#pragma unroll
        for (int nf = 0; nf < 6; nf++) {
            int col = bn + wn * 48 + nf * 8 + (lane & 3) * 2;
            float2 v0 = make_float2(acc[mf][nf][0] + g_bias[col],
                                    acc[mf][nf][1] + g_bias[col + 1]);
            float2 v1 = make_float2(acc[mf][nf][2] + g_bias[col],
                                    acc[mf][nf][3] + g_bias[col + 1]);
            *reinterpret_cast<float2*>(g_Y + (size_t)r0 * NPAD + col) = v0;
            *reinterpret_cast<float2*>(g_Y + (size_t)(r0 + 8) * NPAD + col) = v1;
        }
    }
}

// ----------------------------- epilogue ------------------------------------
__global__ __launch_bounds__(256) void epilogue_kernel(float* __restrict__ out) {
    const int warp = threadIdx.x >> 5;
    const int lane = threadIdx.x & 31;
    const int row  = blockIdx.x * 8 + warp;

    __shared__ float sY[8][352];
    __shared__ float sP[8][288];

    {
        const float4* yr4 = reinterpret_cast<const float4*>(g_Y + (size_t)row * NPAD);
        float4* sy4 = reinterpret_cast<float4*>(sY[warp]);
#pragma unroll
        for (int j = lane; j < 87; j += 32) sy4[j] = yr4[j];
    }
    __syncwarp();
    const float* s = sY[warp];

    float y0v = (lane < NCLS) ? s[lane] : -INFINITY;
    float m = y0v;
#pragma unroll
    for (int o = 16; o; o >>= 1) m = fmaxf(m, __shfl_xor_sync(0xFFFFFFFFu, m, o));
    float e = (lane < NCLS) ? __expf(y0v - m) : 0.f;
    float ssum = e;
#pragma unroll
    for (int o = 16; o; o >>= 1) ssum += __shfl_xor_sync(0xFFFFFFFFu, ssum, o);
    float Pc = e / ssum;

    float best = -1.f;
    int bestk = 0;
    if (lane < NCLS) {
        const float* yc = s + 12 + lane * NCLU;
        float mc = -INFINITY;
#pragma unroll
        for (int k = 0; k < NCLU; k++) mc = fmaxf(mc, yc[k]);
        float sc = 0.f;
#pragma unroll
        for (int k = 0; k < NCLU; k++) sc += __expf(yc[k] - mc);
        float inv = Pc / sc;
#pragma unroll
        for (int k = 0; k < NCLU; k++) {
            float p = __expf(yc[k] - mc) * inv;
            sP[warp][k * NCLS + lane] = p;
            if (p > best) { best = p; bestk = k; }
        }
    }
    __syncwarp();

    // coalesced Plc writes: 72 float4 per row
    {
        const float4* sp4 = reinterpret_cast<const float4*>(sP[warp]);
        float4* po4 = reinterpret_cast<float4*>(out + PLC_OFF + (size_t)row * (NCLU * NCLS));
#pragma unroll
        for (int j = lane; j < 72; j += 32) po4[j] = sp4[j];
    }

    // argmax with first-flat-index tie-break
    float bv = best;
    int bi = bestk * NCLS + lane;
#pragma unroll
    for (int o = 16; o; o >>= 1) {
        float ov = __shfl_xor_sync(0xFFFFFFFFu, bv, o);
        int   oi = __shfl_xor_sync(0xFFFFFFFFu, bi, o);
        if (ov > bv || (ov == bv && oi < bi)) { bv = ov; bi = oi; }
    }
    const int ic = bi % NCLS;

    // candidate-class mask: classes whose per-class best Plc is within thresh of max
    unsigned cmask = __ballot_sync(0xFFFFFFFFu,
                                   (lane < NCLS) && (best >= bv - FLAG_THRESH * bv)) & 0xFFFu;
    if (lane == 0 && (cmask & (cmask - 1))) {   // >1 candidate class
        int p = atomicAdd(&g_flagcnt, 1);
        g_flagrows[p] = row | ((int)cmask << 14);
    }

    if (lane < NCLS) out[Y0_OFF + (size_t)row * NCLS + lane] = s[lane];
    if (lane < NCLU) out[Y1_OFF + (size_t)row * NCLU + lane] = s[12 + ic * NCLU + lane];
    if (lane < NDIM) out[Y2_OFF + (size_t)row * NDIM + lane] = s[300 + ic * NDIM + lane];
}

// ----------------------------- fp32 exact fixup (candidate classes only) ---
__global__ __launch_bounds__(1024) void fixup_kernel(const float* __restrict__ x,
                                                     float* __restrict__ out) {
    __shared__ float sx[N0];
    __shared__ float sy[NCOL];
    __shared__ int   wl[12 + NCLS * NCLU];
    __shared__ int   s_nwork;
    const int tid  = threadIdx.x;
    const int lane = tid & 31;
    const int wid  = tid >> 5;
    const int cnt  = g_flagcnt;

    for (int f = blockIdx.x; f < cnt; f += gridDim.x) {
        const int packed = g_flagrows[f];
        const int row   = packed & 0x3FFF;
        const int cmask = (packed >> 14) & 0xFFF;

        if (tid < 512) {
            *reinterpret_cast<float4*>(&sx[tid * 4]) =
                *reinterpret_cast<const float4*>(x + (size_t)row * N0 + tid * 4);
        }
        if (tid < 12) wl[tid] = tid;
        if (tid < 12 && (cmask >> tid) & 1) {
            int pos = __popc(cmask & ((1 << tid) - 1));
            for (int k = 0; k < NCLU; k++)
                wl[12 + pos * NCLU + k] = 12 + tid * NCLU + k;
        }
        if (tid == 0) s_nwork = 12 + NCLU * __popc(cmask);
        __syncthreads();
        const int nwork = s_nwork;

        for (int w = wid; w < nwork; w += 32) {
            int col = wl[w];
            const float4* wp = reinterpret_cast<const float4*>(&g_Wc[col * N0]);
            const float4* xp = reinterpret_cast<const float4*>(sx);
            float acc = 0.f;
#pragma unroll 8
            for (int i = lane; i < N0 / 4; i += 32) {
                float4 a = xp[i], b = wp[i];
                acc += a.x * b.x + a.y * b.y + a.z * b.z + a.w * b.w;
            }
#pragma unroll
            for (int o = 16; o; o >>= 1) acc += __shfl_xor_sync(0xFFFFFFFFu, acc, o);
            if (lane == 0) sy[col] = acc + g_bias[col];
        }
        __syncthreads();

        if (tid == 0) {
            float mm = -INFINITY;
            for (int c = 0; c < NCLS; c++) mm = fmaxf(mm, sy[c]);
            float ss = 0.f;
            for (int c = 0; c < NCLS; c++) ss += expf(sy[c] - mm);

            float bp = -1.f; int bi = 0x7FFFFFFF;
            for (int c = 0; c < NCLS; c++) {
                if (!((cmask >> c) & 1)) continue;
                float Pc = expf(sy[c] - mm) / ss;
                const float* yc = sy + 12 + c * NCLU;
                float mc = -INFINITY;
                for (int k = 0; k < NCLU; k++) mc = fmaxf(mc, yc[k]);
                float sc = 0.f;
                for (int k = 0; k < NCLU; k++) sc += expf(yc[k] - mc);
                float inv = Pc / sc;
                for (int k = 0; k < NCLU; k++) {
                    float p = expf(yc[k] - mc) * inv;
                    int flat = k * NCLS + c;
                    if (p > bp || (p == bp && flat < bi)) { bp = p; bi = flat; }
                }
            }
            int ic = bi % NCLS;
            const float* yr = g_Y + (size_t)row * NPAD;
            for (int k = 0; k < NCLU; k++)
                out[Y1_OFF + (size_t)row * NCLU + k] = yr[12 + ic * NCLU + k];
            for (int n = 0; n < NDIM; n++)
                out[Y2_OFF + (size_t)row * NDIM + n] = yr[300 + ic * NDIM + n];
        }
        __syncthreads();
    }
}

// ============================================================================
extern "C" void kernel_launch(void* const* d_in, const int* in_sizes, int n_in,
                              void* d_out, int out_size) {
    const float* x    = (const float*)d_in[0];
    const float* Wfc  = (const float*)d_in[1];
    const float* bfc  = (const float*)d_in[2];
    const float* Wbin = (const float*)d_in[3];
    const float* bbin = (const float*)d_in[4];
    const float* Wres = (const float*)d_in[5];
    const float* bres = (const float*)d_in[6];
    float* out = (float*)d_out;

    static bool attr_set = false;
    if (!attr_set) {
        cudaFuncSetAttribute(gemm_kernel, cudaFuncAttributeMaxDynamicSharedMemorySize, SMEM_TOTAL);
        attr_set = true;
    }

    pack_kernel<<<(PACK_TASKS + 255) / 256, 256>>>(Wfc, bfc, Wbin, bbin, Wres, bres);

    gemm_kernel<<<dim3(NPAD / BN, B_ROWS / BM), THREADS, SMEM_TOTAL>>>(x);

    epilogue_kernel<<<B_ROWS / 8, 256>>>(out);

    fixup_kernel<<<1024, 1024>>>(x, out);
}

// round 17
// speedup vs baseline: 1.5253x; 1.3369x over previous
#include <cuda_runtime.h>
#include <cuda_fp16.h>
#include <math.h>
#include <stdint.h>

#define B_ROWS 16384
#define N0     2048
#define NCLS   12
#define NCLU   24
#define NDIM   4
#define NCOL   348
#define NPAD   384

// GEMM tiling
#define BM 128
#define BN 96
#define BK 32
#define THREADS 256
#define KCHUNKS (N0 / BK)     // 64

// smem stage layout (bytes); rows padded to 40 fp16 (80B) => conflict-free ldmatrix
#define ST_AH 0
#define ST_AL 10240           // 128*80
#define ST_BH 20480           // + 96*80 = 7680
#define STAGE 28160
#define SMEM_TOTAL (2 * STAGE)  // 56320

#define FLAG_THRESH 1.5e-3f

// ----------------------------- device scratch ------------------------------
__device__ float g_Wc[NCOL * N0];                  // fp32 packed weights [j][k] (fixup)
__device__ float g_bias[NPAD];
__device__ float g_Y[(size_t)B_ROWS * NPAD];       // GEMM output
__device__ __align__(16) __half g_Bh[NPAD * N0];   // W^T fp16, [n][k]
__device__ int g_flagcnt;
__device__ int g_flagrows[B_ROWS];                 // row | (candidate mask << 14)

// output layout (tuple concat) — validated in round 1
#define Y0_OFF   0
#define Y1_OFF   ((size_t)B_ROWS * 12)
#define Y2_OFF   ((size_t)B_ROWS * 36)
#define PLC_OFF  ((size_t)B_ROWS * 40)

// ----------------------------- PTX helpers ---------------------------------
__device__ __forceinline__ uint32_t smem_u32(const void* p) {
    uint32_t a;
    asm("{ .reg .u64 t; cvta.to.shared.u64 t, %1; cvt.u32.u64 %0, t; }" : "=r"(a) : "l"(p));
    return a;
}
#define CP_ASYNC16(dst, src) \
    asm volatile("cp.async.cg.shared.global [%0], [%1], 16;" :: "r"(dst), "l"(src))
#define CP_COMMIT() asm volatile("cp.async.commit_group;" ::: "memory")
#define CP_WAIT0()  asm volatile("cp.async.wait_group 0;" ::: "memory")

#define LDMATRIX_X4(r0, r1, r2, r3, addr) \
    asm volatile("ldmatrix.sync.aligned.m8n8.x4.shared.b16 {%0,%1,%2,%3}, [%4];" \
                 : "=r"(r0), "=r"(r1), "=r"(r2), "=r"(r3) : "r"(addr))

#define MMA_F16(d, a, b0, b1) \
    asm volatile("mma.sync.aligned.m16n8k16.row.col.f32.f16.f16.f32 " \
                 "{%0,%1,%2,%3}, {%4,%5,%6,%7}, {%8,%9}, {%0,%1,%2,%3};" \
                 : "+f"((d)[0]), "+f"((d)[1]), "+f"((d)[2]), "+f"((d)[3]) \
                 : "r"((a)[0]), "r"((a)[1]), "r"((a)[2]), "r"((a)[3]), "r"(b0), "r"(b1))

// ----------------------------- packing -------------------------------------
__device__ __forceinline__ float colval(int j, int k, const float* Wfc,
                                        const float* Wbin, const float* Wres) {
    if (j < 12) return Wfc[k * NCLS + j];
    if (j < 300) { int t = j - 12, c = t / NCLU, kk = t - c * NCLU;
                   return Wbin[((size_t)c * N0 + k) * NCLU + kk]; }
    if (j < NCOL) { int t = j - 300, c = t / NDIM, n = t - c * NDIM;
                    return Wres[((size_t)c * N0 + k) * NDIM + n]; }
    return 0.f;
}

#define PACK_R2 (NPAD * (N0 / 8))           // fp16 W tasks
#define PACK_R3 (NCOL * (N0 / 4))           // g_Wc float4 tasks
#define PACK_TASKS (PACK_R2 + PACK_R3)

__global__ void pack_kernel(const float* __restrict__ Wfc,  const float* __restrict__ bfc,
                            const float* __restrict__ Wbin, const float* __restrict__ bbin,
                            const float* __restrict__ Wres, const float* __restrict__ bres) {
    int idx = blockIdx.x * blockDim.x + threadIdx.x;
    if (idx == 0) g_flagcnt = 0;
    if (idx < NPAD) {
        float bv = 0.f;
        if (idx < 12) bv = bfc[idx];
        else if (idx < 300) { int t = idx - 12, c = t / NCLU, kk = t - c * NCLU; bv = bbin[c * NCLU + kk]; }
        else if (idx < NCOL) { int t = idx - 300, c = t / NDIM, n = t - c * NDIM; bv = bres[c * NDIM + n]; }
        g_bias[idx] = bv;
    }
    // region 2: fp16 transposed weights [n][k], 8 k per thread
    if (idx < PACK_R2) {
        int n = idx / (N0 / 8);
        int k0 = (idx % (N0 / 8)) * 8;
        float v[8];
#pragma unroll
        for (int e = 0; e < 8; e++) v[e] = colval(n, k0 + e, Wfc, Wbin, Wres);
        uint32_t hp[4];
#pragma unroll
        for (int i = 0; i < 4; i++) {
            __half2 h2 = __floats2half2_rn(v[2*i], v[2*i+1]);
            hp[i] = *reinterpret_cast<uint32_t*>(&h2);
        }
        *reinterpret_cast<uint4*>(&g_Bh[n * N0 + k0]) = make_uint4(hp[0], hp[1], hp[2], hp[3]);
    }
    // region 3: column-major fp32 weights g_Wc[j][k], float4 per thread
    int t3 = idx - PACK_R2;
    if (t3 >= 0 && t3 < PACK_R3) {
        int col = t3 / (N0 / 4);
        int k0  = (t3 % (N0 / 4)) * 4;
        float4 v;
        v.x = colval(col, k0 + 0, Wfc, Wbin, Wres);
        v.y = colval(col, k0 + 1, Wfc, Wbin, Wres);
        v.z = colval(col, k0 + 2, Wfc, Wbin, Wres);
        v.w = colval(col, k0 + 3, Wfc, Wbin, Wres);
        *reinterpret_cast<float4*>(&g_Wc[col * N0 + k0]) = v;
    }
}

// ----------------------------- mma.sync GEMM -------------------------------
// Y[16384][384] = x @ fp16(W) (+bias), 2-term fp16 split of x, fp32 accum.
// Proven round-11 schedule: loadB/loadA -> compute -> storeA -> wait -> sync.
__global__ __launch_bounds__(THREADS) void gemm_kernel(const float* __restrict__ x) {
    extern __shared__ char smem[];
    const uint32_t sb = smem_u32(smem);
    const int tid  = threadIdx.x;
    const int lane = tid & 31;
    const int wid  = tid >> 5;
    const int wm   = wid >> 1;          // 0..3
    const int wn   = wid & 1;           // 0..1
    const int bm   = blockIdx.y * BM;
    const int bn   = blockIdx.x * BN;

    float acc[2][6][4];
#pragma unroll
    for (int i = 0; i < 2; i++)
#pragma unroll
        for (int j = 0; j < 6; j++)
#pragma unroll
            for (int q = 0; q < 4; q++) acc[i][j][q] = 0.f;

    // B: 96 rows x 32 k fp16 = 384 x 16B chunks over 256 threads
    auto loadB = [&](int c, int s) {
        {
            int row = tid >> 2, seg = tid & 3;
            const __half* src = g_Bh + (size_t)(bn + row) * N0 + c * BK + seg * 8;
            uint32_t dst = sb + s * STAGE + ST_BH + row * 80 + seg * 16;
            CP_ASYNC16(dst, src);
        }
        if (tid < 128) {
            int g = tid + 256;
            int row = g >> 2, seg = g & 3;
            const __half* src = g_Bh + (size_t)(bn + row) * N0 + c * BK + seg * 8;
            uint32_t dst = sb + s * STAGE + ST_BH + row * 80 + seg * 16;
            CP_ASYNC16(dst, src);
        }
        CP_COMMIT();
    };
    float4 areg[4];
    auto loadA = [&](int c) {
#pragma unroll
        for (int it = 0; it < 4; ++it) {
            int idx2 = tid + it * 256;              // 0..1023
            int row = idx2 >> 3, seg = idx2 & 7;
            areg[it] = *reinterpret_cast<const float4*>(
                x + (size_t)(bm + row) * N0 + c * BK + seg * 4);
        }
    };
    auto storeA = [&](int s) {
#pragma unroll
        for (int it = 0; it < 4; ++it) {
            int idx2 = tid + it * 256;
            int row = idx2 >> 3, seg = idx2 & 7;
            float v[4] = {areg[it].x, areg[it].y, areg[it].z, areg[it].w};
            uint32_t hp[2], lp[2];
#pragma unroll
            for (int i = 0; i < 2; i++) {
                __half2 h2 = __floats2half2_rn(v[2*i], v[2*i+1]);
                float r0 = v[2*i]   - __low2float(h2);
                float r1 = v[2*i+1] - __high2float(h2);
                __half2 l2 = __floats2half2_rn(r0, r1);
                hp[i] = *reinterpret_cast<uint32_t*>(&h2);
                lp[i] = *reinterpret_cast<uint32_t*>(&l2);
            }
            char* base = smem + s * STAGE;
            *reinterpret_cast<uint2*>(base + ST_AH + row * 80 + seg * 8) = make_uint2(hp[0], hp[1]);
            *reinterpret_cast<uint2*>(base + ST_AL + row * 80 + seg * 8) = make_uint2(lp[0], lp[1]);
        }
    };

    auto compute = [&](int s) {
        const uint32_t st = sb + s * STAGE;
        const int arow = wm * 32 + (lane & 15);
        const int acol8 = (lane >> 4) * 8;
        const int brow = wn * 48 + ((lane >> 4) & 1) * 8 + (lane & 7);
        const int bcol8 = ((lane >> 3) & 1) * 8;
#pragma unroll
        for (int kk = 0; kk < BK; kk += 16) {
            uint32_t ah[2][4], al[2][4], b[3][4];
#pragma unroll
            for (int mf = 0; mf < 2; mf++) {
                uint32_t ad = st + ST_AH + (arow + mf * 16) * 80 + (kk + acol8) * 2;
                LDMATRIX_X4(ah[mf][0], ah[mf][1], ah[mf][2], ah[mf][3], ad);
                uint32_t adl = st + ST_AL + (arow + mf * 16) * 80 + (kk + acol8) * 2;
                LDMATRIX_X4(al[mf][0], al[mf][1], al[mf][2], al[mf][3], adl);
            }
#pragma unroll
            for (int bq = 0; bq < 3; bq++) {
                uint32_t bd = st + ST_BH + (brow + bq * 16) * 80 + (kk + bcol8) * 2;
                LDMATRIX_X4(b[bq][0], b[bq][1], b[bq][2], b[bq][3], bd);
            }
#pragma unroll
            for (int mf = 0; mf < 2; mf++)
#pragma unroll
                for (int nf = 0; nf < 6; nf++) {
                    int bq = nf >> 1, o = (nf & 1) * 2;
                    MMA_F16(acc[mf][nf], ah[mf], b[bq][o], b[bq][o + 1]);
                    MMA_F16(acc[mf][nf], al[mf], b[bq][o], b[bq][o + 1]);
                }
        }
    };

    loadB(0, 0);
    loadA(0);
    storeA(0);
    CP_WAIT0();
    __syncthreads();
    for (int c = 0; c < KCHUNKS; ++c) {
        int s = c & 1;
        if (c < KCHUNKS - 1) { loadB(c + 1, s ^ 1); loadA(c + 1); }
        compute(s);
        if (c < KCHUNKS - 1) {
            storeA(s ^ 1);
            CP_WAIT0();
            __syncthreads();
        }
    }

#pragma unroll
    for (int mf = 0; mf < 2; mf++) {
        int r0 = bm + wm * 32 + mf * 16 + (lane >> 2);
#pragma unroll
        for (int nf = 0; nf < 6; nf++) {
            int col = bn + wn * 48 + nf * 8 + (lane & 3) * 2;
            float2 v0 = make_float2(acc[mf][nf][0] + g_bias[col],
                                    acc[mf][nf][1] + g_bias[col + 1]);
            float2 v1 = make_float2(acc[mf][nf][2] + g_bias[col],
                                    acc[mf][nf][3] + g_bias[col + 1]);
            *reinterpret_cast<float2*>(g_Y + (size_t)r0 * NPAD + col) = v0;
            *reinterpret_cast<float2*>(g_Y + (size_t)(r0 + 8) * NPAD + col) = v1;
        }
    }
}

// ----------------------------- epilogue ------------------------------------
__global__ __launch_bounds__(256) void epilogue_kernel(float* __restrict__ out) {
    const int warp = threadIdx.x >> 5;
    const int lane = threadIdx.x & 31;
    const int row  = blockIdx.x * 8 + warp;

    __shared__ float sY[8][352];
    __shared__ float sP[8][288];

    {
        const float4* yr4 = reinterpret_cast<const float4*>(g_Y + (size_t)row * NPAD);
        float4* sy4 = reinterpret_cast<float4*>(sY[warp]);
#pragma unroll
        for (int j = lane; j < 87; j += 32) sy4[j] = yr4[j];
    }
    __syncwarp();
    const float* s = sY[warp];

    float y0v = (lane < NCLS) ? s[lane] : -INFINITY;
    float m = y0v;
#pragma unroll
    for (int o = 16; o; o >>= 1) m = fmaxf(m, __shfl_xor_sync(0xFFFFFFFFu, m, o));
    float e = (lane < NCLS) ? __expf(y0v - m) : 0.f;
    float ssum = e;
#pragma unroll
    for (int o = 16; o; o >>= 1) ssum += __shfl_xor_sync(0xFFFFFFFFu, ssum, o);
    float Pc = e / ssum;

    float best = -1.f;
    int bestk = 0;
    if (lane < NCLS) {
        const float* yc = s + 12 + lane * NCLU;
        float mc = -INFINITY;
#pragma unroll
        for (int k = 0; k < NCLU; k++) mc = fmaxf(mc, yc[k]);
        float sc = 0.f;
#pragma unroll
        for (int k = 0; k < NCLU; k++) sc += __expf(yc[k] - mc);
        float inv = Pc / sc;
#pragma unroll
        for (int k = 0; k < NCLU; k++) {
            float p = __expf(yc[k] - mc) * inv;
            sP[warp][k * NCLS + lane] = p;
            if (p > best) { best = p; bestk = k; }
        }
    }
    __syncwarp();

    // coalesced Plc writes: 72 float4 per row
    {
        const float4* sp4 = reinterpret_cast<const float4*>(sP[warp]);
        float4* po4 = reinterpret_cast<float4*>(out + PLC_OFF + (size_t)row * (NCLU * NCLS));
#pragma unroll
        for (int j = lane; j < 72; j += 32) po4[j] = sp4[j];
    }

    // argmax with first-flat-index tie-break
    float bv = best;
    int bi = bestk * NCLS + lane;
#pragma unroll
    for (int o = 16; o; o >>= 1) {
        float ov = __shfl_xor_sync(0xFFFFFFFFu, bv, o);
        int   oi = __shfl_xor_sync(0xFFFFFFFFu, bi, o);
        if (ov > bv || (ov == bv && oi < bi)) { bv = ov; bi = oi; }
    }
    const int ic = bi % NCLS;

    // candidate-class mask: classes whose per-class best Plc is within thresh of max
    unsigned cmask = __ballot_sync(0xFFFFFFFFu,
                                   (lane < NCLS) && (best >= bv - FLAG_THRESH * bv)) & 0xFFFu;
    if (lane == 0 && (cmask & (cmask - 1))) {   // >1 candidate class
        int p = atomicAdd(&g_flagcnt, 1);
        g_flagrows[p] = row | ((int)cmask << 14);
    }

    if (lane < NCLS) out[Y0_OFF + (size_t)row * NCLS + lane] = s[lane];
    if (lane < NCLU) out[Y1_OFF + (size_t)row * NCLU + lane] = s[12 + ic * NCLU + lane];
    if (lane < NDIM) out[Y2_OFF + (size_t)row * NDIM + lane] = s[300 + ic * NDIM + lane];
}

// ----------------------------- fp32 exact fixup (candidate classes only) ---
__global__ __launch_bounds__(1024) void fixup_kernel(const float* __restrict__ x,
                                                     float* __restrict__ out) {
    __shared__ float sx[N0];
    __shared__ float sy[NCOL];
    __shared__ int   wl[12 + NCLS * NCLU];
    __shared__ int   s_nwork;
    const int tid  = threadIdx.x;
    const int lane = tid & 31;
    const int wid  = tid >> 5;
    const int cnt  = g_flagcnt;

    for (int f = blockIdx.x; f < cnt; f += gridDim.x) {
        const int packed = g_flagrows[f];
        const int row   = packed & 0x3FFF;
        const int cmask = (packed >> 14) & 0xFFF;

        if (tid < 512) {
            *reinterpret_cast<float4*>(&sx[tid * 4]) =
                *reinterpret_cast<const float4*>(x + (size_t)row * N0 + tid * 4);
        }
        if (tid < 12) wl[tid] = tid;
        if (tid < 12 && (cmask >> tid) & 1) {
            int pos = __popc(cmask & ((1 << tid) - 1));
            for (int k = 0; k < NCLU; k++)
                wl[12 + pos * NCLU + k] = 12 + tid * NCLU + k;
        }
        if (tid == 0) s_nwork = 12 + NCLU * __popc(cmask);
        __syncthreads();
        const int nwork = s_nwork;

        for (int w = wid; w < nwork; w += 32) {
            int col = wl[w];
            const float4* wp = reinterpret_cast<const float4*>(&g_Wc[col * N0]);
            const float4* xp = reinterpret_cast<const float4*>(sx);
            float acc = 0.f;
#pragma unroll 8
            for (int i = lane; i < N0 / 4; i += 32) {
                float4 a = xp[i], b = wp[i];
                acc += a.x * b.x + a.y * b.y + a.z * b.z + a.w * b.w;
            }
#pragma unroll
            for (int o = 16; o; o >>= 1) acc += __shfl_xor_sync(0xFFFFFFFFu, acc, o);
            if (lane == 0) sy[col] = acc + g_bias[col];
        }
        __syncthreads();

        if (tid == 0) {
            float mm = -INFINITY;
            for (int c = 0; c < NCLS; c++) mm = fmaxf(mm, sy[c]);
            float ss = 0.f;
            for (int c = 0; c < NCLS; c++) ss += expf(sy[c] - mm);

            float bp = -1.f; int bi = 0x7FFFFFFF;
            for (int c = 0; c < NCLS; c++) {
                if (!((cmask >> c) & 1)) continue;
                float Pc = expf(sy[c] - mm) / ss;
                const float* yc = sy + 12 + c * NCLU;
                float mc = -INFINITY;
                for (int k = 0; k < NCLU; k++) mc = fmaxf(mc, yc[k]);
                float sc = 0.f;
                for (int k = 0; k < NCLU; k++) sc += expf(yc[k] - mc);
                float inv = Pc / sc;
                for (int k = 0; k < NCLU; k++) {
                    float p = expf(yc[k] - mc) * inv;
                    int flat = k * NCLS + c;
                    if (p > bp || (p == bp && flat < bi)) { bp = p; bi = flat; }
                }
            }
            int ic = bi % NCLS;
            const float* yr = g_Y + (size_t)row * NPAD;
            for (int k = 0; k < NCLU; k++)
                out[Y1_OFF + (size_t)row * NCLU + k] = yr[12 + ic * NCLU + k];
            for (int n = 0; n < NDIM; n++)
                out[Y2_OFF + (size_t)row * NDIM + n] = yr[300 + ic * NDIM + n];
        }
        __syncthreads();
    }
}

// ============================================================================
extern "C" void kernel_launch(void* const* d_in, const int* in_sizes, int n_in,
                              void* d_out, int out_size) {
    const float* x    = (const float*)d_in[0];
    const float* Wfc  = (const float*)d_in[1];
    const float* bfc  = (const float*)d_in[2];
    const float* Wbin = (const float*)d_in[3];
    const float* bbin = (const float*)d_in[4];
    const float* Wres = (const float*)d_in[5];
    const float* bres = (const float*)d_in[6];
    float* out = (float*)d_out;

    static bool attr_set = false;
    if (!attr_set) {
        cudaFuncSetAttribute(gemm_kernel, cudaFuncAttributeMaxDynamicSharedMemorySize, SMEM_TOTAL);
        attr_set = true;
    }

    pack_kernel<<<(PACK_TASKS + 255) / 256, 256>>>(Wfc, bfc, Wbin, bbin, Wres, bres);

    gemm_kernel<<<dim3(NPAD / BN, B_ROWS / BM), THREADS, SMEM_TOTAL>>>(x);

    epilogue_kernel<<<B_ROWS / 8, 256>>>(out);

    fixup_kernel<<<1024, 1024>>>(x, out);
}